// round 16
// baseline (speedup 1.0000x reference)
#include <cuda_runtime.h>
#include <cstdint>

typedef unsigned int u32;
typedef unsigned long long u64;

#define NT 512
#define SLEN 65544
#define NEMB 65536

// ---------------- scratch (device globals; no allocation) ----------------
__device__ __align__(16) u32 g_exp[(NEMB * 256) / 4];  // decoded exponent bytes
__device__ u32 g_man[(NEMB * 256) / 4];                // packed mantissa bytes

// pack 4 raw int32 "bytes" big-endian-first into one u32 (first byte at MSB)
__device__ __forceinline__ u32 pack_be(int4 v) {
    u32 t1 = __byte_perm((u32)v.z, (u32)v.w, 0x0004); // b0=w0, b1=z0
    u32 t2 = __byte_perm((u32)v.x, (u32)v.y, 0x0004); // b0=y0, b1=x0
    return __byte_perm(t1, t2, 0x5410);               // [x0 y0 z0 w0]
}

// one rANS symbol. Shifting-window design: w64 keeps the unconsumed stream
// left-aligned (MSB = next byte), so T = w64>>32 is ready AT SYMBOL START and
// the renorm candidates are single PRMTs issuing in parallel with the ISETPs.
// (Best-measured body: ~85 cyc/symbol at 512x32.)
#define DECODE_SYM(state, w64, fill, accw, byte_i) do {                      \
    u32 slot = (state) & 4095u;                                              \
    uint2 e = LUT[slot];                  /* on-chain LDS.64 */              \
    u32 sym = (u32)SYMT[slot];            /* off-chain */                    \
    u32 T = (u32)((w64) >> 32);           /* next bytes: T.b3=b0, T.b2=b1 */ \
    u32 d = e.x * ((state) >> 12) + e.y;  /* freq*(state>>12)+bias */        \
    u32 c1 = __byte_perm(d, T, 0x2107);   /* (d<<8)|b0        : 1 PRMT */   \
    u32 c2 = __byte_perm(d, T, 0x1076);   /* (d<<16)|b0b1     : 1 PRMT */   \
    bool p1 = d < (1u << 23);                                                \
    bool p2 = d < (1u << 15);             /* implies p1 */                   \
    u32 t = p2 ? c2 : c1;                                                    \
    (state) = p1 ? t : d;                                                    \
    u32 sh = p1 ? (p2 ? 16u : 8u) : 0u;   /* parallel short cycle */         \
    (w64) <<= sh;                                                            \
    (fill) -= (int)p1 + (int)p2;                                             \
    (accw) |= sym << (8 * (byte_i));                                         \
} while (0)

// branchless refill every 2 symbols: splice 4 bytes right below the `fill`
// valid top bytes whenever fill <= 4. LDG unconditional + clamped.
#define REFILL(w64, fill, nb, pf, idx, sp) do {                              \
    bool need = (fill) <= 4;                                                 \
    u32 f4 = need ? (u32)(fill) : 4u;                                        \
    u64 spl = ((u64)(nb)) << (32u - 8u * f4);                                \
    (w64) = need ? ((w64) | spl) : (w64);                                    \
    (fill) = need ? (fill) + 4 : (fill);                                     \
    u32 nb2 = pack_be(pf);                /* off-chain PRMTs */              \
    (nb) = need ? nb2 : (nb);                                                \
    (idx) += need ? 1 : 0;                                                   \
    int ci = (idx) < 16385 ? (idx) : 16385;  /* clamp: never read OOB */     \
    (pf) = __ldg((sp) + ci);                                                 \
} while (0)

// ---------------- fused decode + LUT build + mantissa pack ----------------
// 512 CTAs x 64 threads. All threads build the smem LUT straight from the
// global tables (no separate build kernel). Then:
//   warp 0, lane 0 (SMSP 0): runs the serial rANS chain (R13 body, verbatim)
//   warp 1       (SMSP 1) : packs this CTA's 1/512 slice of the mantissa
//                           array -- fully hidden under the 1.4 ms chain,
//                           and on a different SMSP so it never steals the
//                           chain's issue slots.
__global__ void __launch_bounds__(64, 1)
k_decode(const int* __restrict__ stream,
         const int* __restrict__ tile_offsets,
         const int* __restrict__ states,
         const int* __restrict__ tables,
         const int* __restrict__ slot_map,
         const int4* __restrict__ manraw) {
    __shared__ uint2 LUT[4096];
    __shared__ unsigned char SYMT[4096];
    int tid = threadIdx.x;
#pragma unroll 4
    for (int i = tid; i < 4096; i += 64) {
        u32 sym = (u32)__ldg(slot_map + i);
        u32 t = (u32)__ldg(tables + sym);
        LUT[i] = make_uint2(t >> 16, (u32)i - (t & 0xFFFFu));
        SYMT[i] = (unsigned char)sym;
    }
    __syncthreads();

    if (tid >= 32) {
        // warp 1: pack mantissa slice [bid*8192, bid*8192+8192) of u32 words
        int lane = tid & 31;
        int base = blockIdx.x * 8192;
#pragma unroll 8
        for (int k = lane; k < 8192; k += 32) {
            int w = base + k;
            int4 v = __ldg(manraw + w);
            g_man[w] = (u32)(v.x & 0xFF) | ((u32)(v.y & 0xFF) << 8) |
                       ((u32)(v.z & 0xFF) << 16) | ((u32)(v.w & 0xFF) << 24);
        }
        return;
    }
    if (tid != 0) return;

    int tile = blockIdx.x;
    u32 state = (u32)states[tile];
    const int4* sp = (const int4*)(stream + tile_offsets[tile]);

    // left-aligned shifting window + 2-deep refill pipeline
    u64 w64 = ((u64)pack_be(__ldg(sp + 0)) << 32) | (u64)pack_be(__ldg(sp + 1));
    u32 nb = pack_be(__ldg(sp + 2));
    int4 pf = __ldg(sp + 3);
    int idx = 3;      // int4 index pf currently holds
    int fill = 8;     // valid bytes in w64 (>=4 at every pair start)

    int rt = tile >> 3, ct = tile & 7;
    uint4* outp = (uint4*)g_exp;
    u32 ob = (u32)rt * 16384u + (u32)ct * 2u;  // uint4 index for (k=0, half=0)

    for (int i = 0; i < 2048; ++i) {           // 16 symbols per iteration
        u32 wacc[4];
#pragma unroll
        for (int j = 0; j < 4; ++j) {          // one output u32 word = 4 symbols
            u32 accw = 0;
#pragma unroll
            for (int g = 0; g < 2; ++g) {      // 2 symbols + refill
                DECODE_SYM(state, w64, fill, accw, 2 * g + 0);
                DECODE_SYM(state, w64, fill, accw, 2 * g + 1);
                REFILL(w64, fill, nb, pf, idx, sp);
            }
            wacc[j] = accw;
        }
        outp[ob] = make_uint4(wacc[0], wacc[1], wacc[2], wacc[3]);
        ob += (i & 1) ? 15u : 1u;              // half0->half1: +1; then next k: +15
    }
}

// ---------------- gather: out[l, :] = f32(bf16(exp<<8 | man)) of row x[l] ----------------
__global__ void __launch_bounds__(256)
k_gather(const int* __restrict__ x, float4* __restrict__ out) {
    int l = blockIdx.x * 4 + (threadIdx.x >> 6);
    int c = threadIdx.x & 63;
    int row = x[l];
    u32 e = g_exp[row * 64 + c];
    u32 m = g_man[row * 64 + c];
    float4 o;
    o.x = __uint_as_float(((e & 0xFFu) << 24) | ((m & 0xFFu) << 16));
    o.y = __uint_as_float((((e >> 8) & 0xFFu) << 24) | (((m >> 8) & 0xFFu) << 16));
    o.z = __uint_as_float((((e >> 16) & 0xFFu) << 24) | (((m >> 16) & 0xFFu) << 16));
    o.w = __uint_as_float((e & 0xFF000000u) | ((m >> 24) << 16));
    out[(size_t)l * 64 + (size_t)c] = o;
}

// ---------------- launch ----------------
extern "C" void kernel_launch(void* const* d_in, const int* in_sizes, int n_in,
                              void* d_out, int out_size) {
    const int* x       = (const int*)d_in[0];
    const int* stream  = (const int*)d_in[1];
    const int* states  = (const int*)d_in[2];
    const int* tables  = (const int*)d_in[3];
    const int* slotmap = (const int*)d_in[4];
    const int* toffs   = (const int*)d_in[5];
    // d_in[6] = tile_max_lens (uniform; unused)
    const int* manraw  = (const int*)d_in[7];
    float* out = (float*)d_out;

    k_decode<<<512, 64>>>(stream, toffs, states, tables, slotmap,
                          (const int4*)manraw);
    k_gather<<<65536, 256>>>(x, (float4*)out);
}

// round 17
// speedup vs baseline: 1.2402x; 1.2402x over previous
#include <cuda_runtime.h>
#include <cstdint>

typedef unsigned int u32;
typedef unsigned long long u64;

#define NT 512
#define SLEN 65544
#define NEMB 65536

// ---------------- scratch (device globals; no allocation) ----------------
__device__ u32 g_stream[(NT * SLEN) / 4 + 64];   // packed stream bytes (+pad)
__device__ u32 g_man[(NEMB * 256) / 4];          // packed mantissa bytes
__device__ u32 g_exp[(NEMB * 256) / 4];          // decoded exponent bytes
__device__ uint2 g_lut[4096];                    // {freq, bias = slot - cum}
__device__ u32 g_symtab[4096];

// ---------------- fused prep: LUT build + stream pack + mantissa pack ------
// One launch instead of three. Thread i:
//   i < 4096     : also builds LUT entry i
//   i < n4s      : packs stream word i
//   i < n4m      : packs mantissa word i
__global__ void __launch_bounds__(256)
k_prep(const int4* __restrict__ stream_in, const int4* __restrict__ man_in,
       const int* __restrict__ tables, const int* __restrict__ slot_map,
       int n4s, int n4m) {
    int i = blockIdx.x * blockDim.x + threadIdx.x;
    if (i < 4096) {
        u32 sym = (u32)__ldg(slot_map + i);
        u32 t = (u32)__ldg(tables + (int)sym);
        g_lut[i] = make_uint2(t >> 16, (u32)i - (t & 0xFFFFu));
        g_symtab[i] = sym;
    }
    if (i < n4s) {
        int4 v = __ldg(stream_in + i);
        g_stream[i] = (u32)(v.x & 0xFF) | ((u32)(v.y & 0xFF) << 8) |
                      ((u32)(v.z & 0xFF) << 16) | ((u32)(v.w & 0xFF) << 24);
    }
    if (i < n4m) {
        int4 v = __ldg(man_in + i);
        g_man[i] = (u32)(v.x & 0xFF) | ((u32)(v.y & 0xFF) << 8) |
                   ((u32)(v.z & 0xFF) << 16) | ((u32)(v.w & 0xFF) << 24);
    }
}

// byte-swap an 8-byte little-endian load so the FIRST stream byte sits at the MSB
__device__ __forceinline__ u64 bswap_pair(uint2 v) {
    u32 hiw = __byte_perm(v.x, 0, 0x0123);
    u32 low = __byte_perm(v.y, 0, 0x0123);
    return ((u64)hiw << 32) | (u64)low;
}

// ---------------- the serial rANS decode (R3 config, best measured) --------
// 512 one-warp CTAs; lane 0 runs the chain alone. 85 cyc/symbol measured.
// DO NOT add co-resident work to this kernel (R16 regression).
__global__ void __launch_bounds__(32, 1)
k_decode(const int* __restrict__ tile_offsets, const int* __restrict__ states) {
    __shared__ uint2 LUT[4096];
    __shared__ unsigned char SYMT[4096];
    int tid = threadIdx.x;
#pragma unroll 4
    for (int i = tid; i < 4096; i += 32) {
        LUT[i] = g_lut[i];
        SYMT[i] = (unsigned char)g_symtab[i];
    }
    __syncthreads();
    if (tid != 0) return;

    int tile = blockIdx.x;
    u32 state = (u32)states[tile];
    const uint2* sp = (const uint2*)(g_stream + (tile_offsets[tile] >> 2));

    // 16-byte register reservoir (left-aligned, MSB = next stream byte)
    // + 3-deep prefetch stage so refill never waits on L2/DRAM
    u64 hi = bswap_pair(__ldg(sp + 0));
    u64 lo = bswap_pair(__ldg(sp + 1));
    u64 n0 = bswap_pair(__ldg(sp + 2));
    u64 n1 = bswap_pair(__ldg(sp + 3));
    u64 n2 = bswap_pair(__ldg(sp + 4));
    int ptr = 5;     // u64 units
    int avail = 16;  // valid bytes in (hi:lo)

    // output word index: row = (tile>>3)*1024 + (blk>>3), colword = (tile&7)*8 + (blk&7)
    u32 outw = (u32)((tile >> 3) * 1024) * 64u + (u32)(tile & 7) * 8u;

    for (int blk = 0; blk < 8192; ++blk) {
        uint2 fresh = __ldg(sp + ptr);  // early prefetch; merged (or discarded) at block end
        u32 acc = 0;
#pragma unroll
        for (int s = 0; s < 4; ++s) {
            u32 slot = state & 4095u;
            uint2 e = LUT[slot];                 // LDS.64 on the critical chain
            u32 sym = (u32)SYMT[slot];           // off critical path
            state = e.x * (state >> 12) + e.y;   // freq*(state>>12) + bias
            u32 b0 = (u32)(hi >> 56);
            u32 b01 = (u32)(hi >> 48);
            bool p1 = state < (1u << 23);        // need >=1 renorm byte
            bool p2 = state < (1u << 15);        // need exactly 2 (implies p1)
            u32 c1 = (state << 8) | b0;
            u32 c2 = (state << 16) | b01;
            u32 ns = p1 ? c1 : state;
            ns = p2 ? c2 : ns;
            // consume 0/1/2 bytes from reservoir (off critical path)
            u64 h1 = (hi << 8) | (lo >> 56);
            u64 l1 = lo << 8;
            hi = p1 ? h1 : hi;
            lo = p1 ? l1 : lo;
            u64 h2 = (hi << 8) | (lo >> 56);
            u64 l2 = lo << 8;
            hi = p2 ? h2 : hi;
            lo = p2 ? l2 : lo;
            avail -= (int)p1 + (int)p2;
            state = ns;
            acc |= sym << (8 * s);
        }
        g_exp[outw] = acc;
        outw += ((blk & 7) == 7) ? 57u : 1u;

        // branchless refill: append n0's 8 bytes at byte position `avail` when avail<8
        bool need = avail < 8;
        unsigned a = need ? (unsigned)avail : 8u;
        unsigned a4 = a * 4u;          // <= 32, double-shift avoids shift-by-64 UB
        unsigned s4 = (8u - a) * 4u;   // <= 32
        u64 add_hi = (n0 >> a4) >> a4;
        u64 add_lo = (n0 << s4) << s4;
        hi = need ? (hi | add_hi) : hi;
        lo = need ? (lo | add_lo) : lo;
        n0 = need ? n1 : n0;
        n1 = need ? n2 : n1;
        n2 = need ? bswap_pair(fresh) : n2;
        ptr += need ? 1 : 0;
        avail += need ? 8 : 0;
    }
}

// ---------------- gather: out[l, :] = f32(bf16(exp<<8 | man)) of row x[l] ----------------
// Streaming stores (__stcs): the 256MB output is write-once; keep the 33MB
// exp/man working set (4x reuse) resident in L2 instead.
__global__ void __launch_bounds__(256)
k_gather(const int* __restrict__ x, float4* __restrict__ out) {
    int l = blockIdx.x * 4 + (threadIdx.x >> 6);
    int c = threadIdx.x & 63;
    int row = __ldg(x + l);
    u32 e = __ldg(g_exp + row * 64 + c);
    u32 m = __ldg(g_man + row * 64 + c);
    float4 o;
    o.x = __uint_as_float(((e & 0xFFu) << 24) | ((m & 0xFFu) << 16));
    o.y = __uint_as_float((((e >> 8) & 0xFFu) << 24) | (((m >> 8) & 0xFFu) << 16));
    o.z = __uint_as_float((((e >> 16) & 0xFFu) << 24) | (((m >> 16) & 0xFFu) << 16));
    o.w = __uint_as_float((e & 0xFF000000u) | ((m >> 24) << 16));
    __stcs(out + (size_t)l * 64 + (size_t)c, o);
}

// ---------------- launch ----------------
extern "C" void kernel_launch(void* const* d_in, const int* in_sizes, int n_in,
                              void* d_out, int out_size) {
    const int* x       = (const int*)d_in[0];
    const int* stream  = (const int*)d_in[1];
    const int* states  = (const int*)d_in[2];
    const int* tables  = (const int*)d_in[3];
    const int* slotmap = (const int*)d_in[4];
    const int* toffs   = (const int*)d_in[5];
    // d_in[6] = tile_max_lens (uniform; unused)
    const int* manraw  = (const int*)d_in[7];
    float* out = (float*)d_out;

    int n4s = (NT * SLEN) / 4;          // 8,389,632
    int n4m = (NEMB * 256) / 4;         // 4,194,304
    k_prep<<<(n4s + 255) / 256, 256>>>((const int4*)stream, (const int4*)manraw,
                                       tables, slotmap, n4s, n4m);
    k_decode<<<512, 32>>>(toffs, states);
    k_gather<<<65536, 256>>>(x, (float4*)out);
}